// round 11
// baseline (speedup 1.0000x reference)
#include <cuda_runtime.h>
#include <cuda_bf16.h>
#include <math.h>
#include <stdint.h>

// ---------------- problem constants ----------------
#define Bb    2
#define Ss    2048
#define MTOK  4096
#define NBATCH 16
#define SCALE 0.08838834764831845f   // 1/sqrt(128)

// ---------------- scratch (device globals; no allocation) ----------------
__device__ float g_cq[MTOK * 128];
__device__ float g_q[MTOK * 1024];
__device__ float g_ckvkr[MTOK * 192];
__device__ float g_kr[MTOK * 64];
__device__ float g_kv[MTOK * 2560];
__device__ float g_sc[(long long)NBATCH * Ss * Ss];   // 268 MB
// pre-split bf16 operands (hi/lo)
__device__ __nv_bfloat16 g_xh[MTOK * 1024],   g_xl[MTOK * 1024];
__device__ __nv_bfloat16 g_cqh[MTOK * 128],   g_cql[MTOK * 128];
__device__ __nv_bfloat16 g_ckvh[MTOK * 128],  g_ckvl[MTOK * 128];
__device__ __nv_bfloat16 g_qsh[NBATCH * Ss * 128], g_qsl[NBATCH * Ss * 128];
__device__ __nv_bfloat16 g_ksh[NBATCH * Ss * 128], g_ksl[NBATCH * Ss * 128];
__device__ __nv_bfloat16 g_vth[NBATCH * 256 * Ss], g_vtl[NBATCH * 256 * Ss];
__device__ __nv_bfloat16 g_ph[(long long)NBATCH * Ss * Ss];   // 134 MB
__device__ __nv_bfloat16 g_pl[(long long)NBATCH * Ss * Ss];   // 134 MB
__device__ __nv_bfloat16 g_attnh[MTOK * 2048], g_attnl[MTOK * 2048];
__device__ __nv_bfloat16 g_wdqh[128 * 1024],  g_wdql[128 * 1024];
__device__ __nv_bfloat16 g_wuqh[1024 * 128],  g_wuql[1024 * 128];
__device__ __nv_bfloat16 g_wdkvh[192 * 1024], g_wdkvl[192 * 1024];
__device__ __nv_bfloat16 g_wukuvh[2560 * 128], g_wukuvl[2560 * 128];
__device__ __nv_bfloat16 g_woh[1024 * 2048],  g_wol[1024 * 2048];

// ================= helpers =================
__device__ __forceinline__ uint32_t smem_u32(const void* p) {
    uint32_t a;
    asm("{ .reg .u64 t; cvta.to.shared.u64 t, %1; cvt.u32.u64 %0, t; }" : "=r"(a) : "l"(p));
    return a;
}

#define LDSM4(r0, r1, r2, r3, addr) \
    asm volatile("ldmatrix.sync.aligned.m8n8.x4.shared.b16 {%0,%1,%2,%3}, [%4];" \
                 : "=r"(r0), "=r"(r1), "=r"(r2), "=r"(r3) : "r"(addr))

#define MMA_BF16(d, a, b) \
    asm volatile("mma.sync.aligned.m16n8k16.row.col.f32.bf16.bf16.f32 " \
                 "{%0,%1,%2,%3}, {%4,%5,%6,%7}, {%8,%9}, {%0,%1,%2,%3};" \
                 : "+f"((d)[0]), "+f"((d)[1]), "+f"((d)[2]), "+f"((d)[3]) \
                 : "r"((a)[0]), "r"((a)[1]), "r"((a)[2]), "r"((a)[3]), \
                   "r"((b)[0]), "r"((b)[1]))

__device__ __forceinline__ void split2(float x, float y, uint32_t& hi, uint32_t& lo) {
    __nv_bfloat16 hx = __float2bfloat16(x), hy = __float2bfloat16(y);
    __nv_bfloat16 lx = __float2bfloat16(x - __bfloat162float(hx));
    __nv_bfloat16 ly = __float2bfloat16(y - __bfloat162float(hy));
    __nv_bfloat162 h = __halves2bfloat162(hx, hy);
    __nv_bfloat162 l = __halves2bfloat162(lx, ly);
    hi = *reinterpret_cast<uint32_t*>(&h);
    lo = *reinterpret_cast<uint32_t*>(&l);
}
__device__ __forceinline__ void cpa16(uint32_t dst, const void* src) {
    asm volatile("cp.async.cg.shared.global [%0], [%1], 16;" :: "r"(dst), "l"(src));
}
#define CP_COMMIT() asm volatile("cp.async.commit_group;" ::: "memory")
#define CP_WAIT0()  asm volatile("cp.async.wait_group 0;" ::: "memory")

// ================= pure-bf16 double-buffered 3-pass GEMM =================
// C[m,n] = alpha * sum_k A[m,k]*B[n,k] + bias[n]
// A, B both pre-split bf16 hi/lo, loaded via cp.async. fp32 accum.
// Block 128x128, BK=32, 256 threads (8 warps 2m x 4n). M%128==0, K%32==0.
// MODE 0: fp32 C output.  MODE 1: split bf16 output into Ch/Cl with
//         attention permute layout [b*Ss + m][h*256 + n] (z = b*8+h, N=256).
#define SROW 40                               // bf16 per smem row (80 B)
#define TILE_B ((uint32_t)(128 * SROW * 2))   // 10240 B per tile
#define STAGE_B (4 * TILE_B)                  // Ah, Al, Bh, Bl
#define GEMM_SMEM (2 * STAGE_B)               // 81920

template <int MODE>
__global__ void __launch_bounds__(256)
hgemm3_kernel(const __nv_bfloat16* __restrict__ Ah_,
              const __nv_bfloat16* __restrict__ Al_, int lda, long long sA,
              const __nv_bfloat16* __restrict__ Bh_,
              const __nv_bfloat16* __restrict__ Bl_, int ldb, long long sB,
              const float* __restrict__ bias,
              float* __restrict__ C, int ldc, long long sC,
              __nv_bfloat16* __restrict__ Ch, __nv_bfloat16* __restrict__ Cl,
              int N, int K, float alpha)
{
    extern __shared__ char smraw[];
    const uint32_t sb = smem_u32(smraw);

    const int tid  = threadIdx.x;
    const int lane = tid & 31;
    const int wid  = tid >> 5;
    const int wm   = wid & 1;
    const int wn   = wid >> 1;

    const int z  = blockIdx.z;
    Ah_ += z * sA;  Al_ += z * sA;
    Bh_ += z * sB;  Bl_ += z * sB;
    const int m0 = blockIdx.y * 128;
    const int n0 = blockIdx.x * 128;

    float acc[4][4][4];
#pragma unroll
    for (int i = 0; i < 4; i++)
#pragma unroll
        for (int j = 0; j < 4; j++)
#pragma unroll
            for (int c = 0; c < 4; c++) acc[i][j][c] = 0.f;

#define BUF_AH(t) (sb + (t) * STAGE_B)
#define BUF_AL(t) (sb + (t) * STAGE_B + TILE_B)
#define BUF_BH(t) (sb + (t) * STAGE_B + 2 * TILE_B)
#define BUF_BL(t) (sb + (t) * STAGE_B + 3 * TILE_B)

#define LOAD_AB(kt, t)                                                          \
    {                                                                           \
        _Pragma("unroll")                                                       \
        for (int u = 0; u < 2; u++) {                                           \
            int id = tid * 2 + u;                                               \
            int r  = id >> 2;                                                   \
            int cc = (id & 3) * 8;                                              \
            uint32_t doff = (uint32_t)(r * SROW + cc) * 2;                      \
            long long ga = (long long)(m0 + r) * lda + (kt) + cc;               \
            cpa16(BUF_AH(t) + doff, Ah_ + ga);                                  \
            cpa16(BUF_AL(t) + doff, Al_ + ga);                                  \
            int gn = n0 + r;                                                    \
            if (gn < N) {                                                       \
                long long gb = (long long)gn * ldb + (kt) + cc;                 \
                cpa16(BUF_BH(t) + doff, Bh_ + gb);                              \
                cpa16(BUF_BL(t) + doff, Bl_ + gb);                              \
            } else {                                                            \
                asm volatile("st.shared.v4.b32 [%0], {%1,%1,%1,%1};" ::         \
                             "r"(BUF_BH(t) + doff), "r"(0) : "memory");         \
                asm volatile("st.shared.v4.b32 [%0], {%1,%1,%1,%1};" ::         \
                             "r"(BUF_BL(t) + doff), "r"(0) : "memory");         \
            }                                                                   \
        }                                                                       \
    }

    // ---- prologue ----
    LOAD_AB(0, 0);
    CP_COMMIT();
    CP_WAIT0();
    __syncthreads();

    const int nk = K >> 5;
    for (int s = 0; s < nk; s++) {
        const int cur = s & 1, nxt = cur ^ 1;
        if (s + 1 < nk) {
            LOAD_AB((s + 1) << 5, nxt);
            CP_COMMIT();
        }

        const uint32_t uAh = BUF_AH(cur), uAl = BUF_AL(cur);
        const uint32_t uBh = BUF_BH(cur), uBl = BUF_BL(cur);
#pragma unroll
        for (int ks = 0; ks < 2; ks++) {
            uint32_t bh[4][2], bl[4][2];
#pragma unroll
            for (int jp = 0; jp < 2; jp++) {
                int rowb = wn * 32 + jp * 16 + (lane & 7) + ((lane & 16) >> 1);
                int kc   = ks * 16 + (lane & 8);
                uint32_t off = (uint32_t)(rowb * SROW + kc) * 2;
                LDSM4(bh[jp * 2][0], bh[jp * 2][1], bh[jp * 2 + 1][0], bh[jp * 2 + 1][1],
                      uBh + off);
                LDSM4(bl[jp * 2][0], bl[jp * 2][1], bl[jp * 2 + 1][0], bl[jp * 2 + 1][1],
                      uBl + off);
            }
#pragma unroll
            for (int i = 0; i < 4; i++) {
                int rowa = wm * 64 + i * 16 + (lane & 7) + (lane & 8);
                int kc   = ks * 16 + ((lane & 16) >> 1);
                uint32_t off = (uint32_t)(rowa * SROW + kc) * 2;
                uint32_t ah[4], al[4];
                LDSM4(ah[0], ah[1], ah[2], ah[3], uAh + off);
                LDSM4(al[0], al[1], al[2], al[3], uAl + off);
#pragma unroll
                for (int j = 0; j < 4; j++) {
                    MMA_BF16(acc[i][j], ah, bh[j]);
                    MMA_BF16(acc[i][j], ah, bl[j]);
                    MMA_BF16(acc[i][j], al, bh[j]);
                }
            }
        }

        if (s + 1 < nk) CP_WAIT0();
        __syncthreads();
    }

    // ---- epilogue ----
    if (MODE == 0) {
        float* Cp = C + z * sC;
#pragma unroll
        for (int j = 0; j < 4; j++) {
            int col = n0 + wn * 32 + j * 8 + (lane & 3) * 2;
            if (col >= N) continue;
            float b0 = 0.f, b1 = 0.f;
            if (bias) { b0 = bias[col]; b1 = bias[col + 1]; }
#pragma unroll
            for (int i = 0; i < 4; i++) {
                int row = m0 + wm * 64 + i * 16 + (lane >> 2);
                float2 v0 = make_float2(acc[i][j][0] * alpha + b0,
                                        acc[i][j][1] * alpha + b1);
                float2 v1 = make_float2(acc[i][j][2] * alpha + b0,
                                        acc[i][j][3] * alpha + b1);
                *reinterpret_cast<float2*>(Cp + (long long)row * ldc + col)       = v0;
                *reinterpret_cast<float2*>(Cp + (long long)(row + 8) * ldc + col) = v1;
            }
        }
    } else {
        // split + permute: z = b*8 + h
        long long base = ((long long)(z >> 3) * Ss) * 2048 + (z & 7) * 256;
#pragma unroll
        for (int j = 0; j < 4; j++) {
            int col = n0 + wn * 32 + j * 8 + (lane & 3) * 2;
#pragma unroll
            for (int i = 0; i < 4; i++) {
                int row = m0 + wm * 64 + i * 16 + (lane >> 2);
                uint32_t h0, l0, h1, l1;
                split2(acc[i][j][0], acc[i][j][1], h0, l0);
                split2(acc[i][j][2], acc[i][j][3], h1, l1);
                long long o0 = base + (long long)row * 2048 + col;
                long long o1 = base + (long long)(row + 8) * 2048 + col;
                *reinterpret_cast<uint32_t*>(Ch + o0) = h0;
                *reinterpret_cast<uint32_t*>(Cl + o0) = l0;
                *reinterpret_cast<uint32_t*>(Ch + o1) = h1;
                *reinterpret_cast<uint32_t*>(Cl + o1) = l1;
            }
        }
    }
#undef BUF_AH
#undef BUF_AL
#undef BUF_BH
#undef BUF_BL
#undef LOAD_AB
}

// ================= producer / prep kernels =================
// split x (fp32 -> hi/lo bf16), 4 floats per thread
__global__ void split_x_kernel(const float* __restrict__ src,
                               __nv_bfloat16* __restrict__ dh,
                               __nv_bfloat16* __restrict__ dl)
{
    int idx = blockIdx.x * blockDim.x + threadIdx.x;
    float4 v = *reinterpret_cast<const float4*>(src + idx * 4);
    uint32_t h0, l0, h1, l1;
    split2(v.x, v.y, h0, l0);
    split2(v.z, v.w, h1, l1);
    uint2 hh = make_uint2(h0, h1), ll = make_uint2(l0, l1);
    *reinterpret_cast<uint2*>(dh + idx * 4) = hh;
    *reinterpret_cast<uint2*>(dl + idx * 4) = ll;
}

// transpose + split: fp32 [R][C] -> bf16 hi/lo [C][R]
__global__ void transpose_split_kernel(const float* __restrict__ src, int R, int Cc,
                                       __nv_bfloat16* __restrict__ dh,
                                       __nv_bfloat16* __restrict__ dl)
{
    __shared__ float t[32][33];
    int r0 = blockIdx.y * 32, c0 = blockIdx.x * 32;
    int tx = threadIdx.x, ty = threadIdx.y;    // 32 x 8
#pragma unroll
    for (int i = 0; i < 32; i += 8)
        if (r0 + ty + i < R && c0 + tx < Cc)
            t[ty + i][tx] = src[(long long)(r0 + ty + i) * Cc + c0 + tx];
    __syncthreads();
#pragma unroll
    for (int i = 0; i < 32; i += 8)
        if (c0 + ty + i < Cc && r0 + tx < R) {
            float v = t[tx][ty + i];
            __nv_bfloat16 h = __float2bfloat16(v);
            long long o = (long long)(c0 + ty + i) * R + r0 + tx;
            dh[o] = h;
            dl[o] = __float2bfloat16(v - __bfloat162float(h));
        }
}

// V^T split: vt[z][d][s] from kv[(b*2048+s)*2560 + 512 + h*256 + d]
__global__ void build_vT_split_kernel(const float* __restrict__ kv,
                                      __nv_bfloat16* __restrict__ vh,
                                      __nv_bfloat16* __restrict__ vl)
{
    __shared__ float t[32][33];
    int z = blockIdx.z, b = z >> 3, h = z & 7;
    const float* src = kv + (long long)b * 2048 * 2560 + 512 + h * 256;
    long long dbase = (long long)z * 256 * 2048;
    int s0 = blockIdx.x * 32, d0 = blockIdx.y * 32;
    int tx = threadIdx.x, ty = threadIdx.y;
#pragma unroll
    for (int i = 0; i < 32; i += 8)
        t[ty + i][tx] = src[(long long)(s0 + ty + i) * 2560 + d0 + tx];
    __syncthreads();
#pragma unroll
    for (int i = 0; i < 32; i += 8) {
        float v = t[tx][ty + i];
        __nv_bfloat16 hh = __float2bfloat16(v);
        long long o = dbase + (long long)(d0 + ty + i) * 2048 + s0 + tx;
        vh[o] = hh;
        vl[o] = __float2bfloat16(v - __bfloat162float(hh));
    }
}

// rmsnorm over 128 cols, split output
__global__ void rmsnorm_split_kernel(const float* __restrict__ buf,
                                     const float* __restrict__ w,
                                     __nv_bfloat16* __restrict__ oh,
                                     __nv_bfloat16* __restrict__ ol)
{
    int row = blockIdx.x, tid = threadIdx.x;
    float v = buf[row * 128 + tid];
    float ss = v * v;
#pragma unroll
    for (int o = 16; o; o >>= 1) ss += __shfl_xor_sync(0xffffffffu, ss, o);
    __shared__ float red[4];
    if ((tid & 31) == 0) red[tid >> 5] = ss;
    __syncthreads();
    float tot = red[0] + red[1] + red[2] + red[3];
    float rs = rsqrtf(tot * (1.f / 128.f) + 1e-8f);
    float ov = w[tid] * v * rs;
    __nv_bfloat16 h = __float2bfloat16(ov);
    oh[row * 128 + tid] = h;
    ol[row * 128 + tid] = __float2bfloat16(ov - __bfloat162float(h));
}

// ckv rmsnorm (split out) + k_rope rope (fp32 out)
__global__ void post_ckvkr_kernel(const float* __restrict__ in,
                                  const float* __restrict__ w,
                                  const int* __restrict__ pos,
                                  __nv_bfloat16* __restrict__ ckvh,
                                  __nv_bfloat16* __restrict__ ckvl,
                                  float* __restrict__ kr)
{
    int row = blockIdx.x, tid = threadIdx.x;
    float v = in[row * 192 + tid];
    float ss = v * v;
#pragma unroll
    for (int o = 16; o; o >>= 1) ss += __shfl_xor_sync(0xffffffffu, ss, o);
    __shared__ float red[4];
    if ((tid & 31) == 0) red[tid >> 5] = ss;
    __syncthreads();
    float tot = red[0] + red[1] + red[2] + red[3];
    float rs = rsqrtf(tot * (1.f / 128.f) + 1e-8f);
    float ov = w[tid] * v * rs;
    __nv_bfloat16 h = __float2bfloat16(ov);
    ckvh[row * 128 + tid] = h;
    ckvl[row * 128 + tid] = __float2bfloat16(ov - __bfloat162float(h));

    if (tid < 32) {
        float xe = in[row * 192 + 128 + 2 * tid];
        float xo = in[row * 192 + 128 + 2 * tid + 1];
        float invf = powf(10000.f, -(float)(2 * tid) / 64.f);
        float ang = (float)pos[row] * invf;
        float s, c;
        sincosf(ang, &s, &c);
        kr[row * 64 + 2 * tid]     = xe * c - xo * s;
        kr[row * 64 + 2 * tid + 1] = xe * s + xo * c;
    }
}

// build q_states [16][2048][128] with rope, split output
__global__ void build_q_split_kernel(const float* __restrict__ q,
                                     const int* __restrict__ pos,
                                     __nv_bfloat16* __restrict__ qh,
                                     __nv_bfloat16* __restrict__ ql)
{
    int idx = blockIdx.x * blockDim.x + threadIdx.x;
    int d = idx & 127;
    int t = idx >> 7;
    int qp = t & (Ss - 1);
    int zz = t >> 11;
    int b = zz >> 3, h = zz & 7;
    int row = b * Ss + qp;
    float val;
    if (d < 96) {
        val = q[row * 1024 + h * 96 + d];
    } else {
        int r = d - 96;
        int i = r >> 1;
        float xe = q[row * 1024 + 768 + h * 32 + 2 * i];
        float xo = q[row * 1024 + 768 + h * 32 + 2 * i + 1];
        float invf = powf(10000.f, -(float)(2 * i) / 32.f);
        float ang = (float)pos[row] * invf;
        float s, c;
        sincosf(ang, &s, &c);
        val = (r & 1) ? (xe * s + xo * c) : (xe * c - xo * s);
    }
    __nv_bfloat16 hh = __float2bfloat16(val);
    qh[idx] = hh;
    ql[idx] = __float2bfloat16(val - __bfloat162float(hh));
}

// build k_states split
__global__ void build_k_split_kernel(const float* __restrict__ kv,
                                     const float* __restrict__ kr,
                                     __nv_bfloat16* __restrict__ kh,
                                     __nv_bfloat16* __restrict__ kl)
{
    int idx = blockIdx.x * blockDim.x + threadIdx.x;
    int d = idx & 127;
    int t = idx >> 7;
    int qp = t & (Ss - 1);
    int zz = t >> 11;
    int b = zz >> 3, h = zz & 7;
    int row = b * Ss + qp;
    float v = (d < 64) ? kv[row * 2560 + h * 64 + d] : kr[row * 64 + (d - 64)];
    __nv_bfloat16 hh = __float2bfloat16(v);
    kh[idx] = hh;
    kl[idx] = __float2bfloat16(v - __bfloat162float(hh));
}

// row softmax over 2048 cols, split bf16 output
__global__ void softmax_split_kernel(const float* __restrict__ sc,
                                     __nv_bfloat16* __restrict__ ph,
                                     __nv_bfloat16* __restrict__ pl)
{
    const float* p = sc + (long long)blockIdx.x * 2048;
    long long obase = (long long)blockIdx.x * 2048;
    int tid = threadIdx.x;
    float v[8];
#pragma unroll
    for (int i = 0; i < 8; i++) v[i] = p[tid + 256 * i];
    float m = v[0];
#pragma unroll
    for (int i = 1; i < 8; i++) m = fmaxf(m, v[i]);
#pragma unroll
    for (int o = 16; o; o >>= 1) m = fmaxf(m, __shfl_xor_sync(0xffffffffu, m, o));
    __shared__ float redm[8];
    int lane = tid & 31, w = tid >> 5;
    if (lane == 0) redm[w] = m;
    __syncthreads();
    m = redm[0];
#pragma unroll
    for (int i = 1; i < 8; i++) m = fmaxf(m, redm[i]);
    float sum = 0.f;
#pragma unroll
    for (int i = 0; i < 8; i++) { v[i] = __expf(v[i] - m); sum += v[i]; }
#pragma unroll
    for (int o = 16; o; o >>= 1) sum += __shfl_xor_sync(0xffffffffu, sum, o);
    __shared__ float reds[8];
    if (lane == 0) reds[w] = sum;
    __syncthreads();
    sum = 0.f;
#pragma unroll
    for (int i = 0; i < 8; i++) sum += reds[i];
    float inv = 1.f / sum;
#pragma unroll
    for (int i = 0; i < 8; i++) {
        float val = v[i] * inv;
        __nv_bfloat16 h = __float2bfloat16(val);
        ph[obase + tid + 256 * i] = h;
        pl[obase + tid + 256 * i] = __float2bfloat16(val - __bfloat162float(h));
    }
}

// ================= launch =================
extern "C" void kernel_launch(void* const* d_in, const int* in_sizes, int n_in,
                              void* d_out, int out_size)
{
    const float* x         = (const float*)d_in[0];
    const int*   pos       = (const int*)  d_in[1];
    const float* w_dq_w    = (const float*)d_in[2];
    const float* w_dq_b    = (const float*)d_in[3];
    const float* q_norm_w  = (const float*)d_in[4];
    const float* w_uq_qr_w = (const float*)d_in[5];
    const float* w_uq_qr_b = (const float*)d_in[6];
    const float* w_dkv_w   = (const float*)d_in[7];
    const float* w_dkv_b   = (const float*)d_in[8];
    const float* kv_norm_w = (const float*)d_in[9];
    const float* w_ukuv_w  = (const float*)d_in[10];
    const float* w_ukuv_b  = (const float*)d_in[11];
    const float* w_o_w     = (const float*)d_in[12];
    const float* w_o_b     = (const float*)d_in[13];
    float* out = (float*)d_out;

    float *p_cq, *p_q, *p_ckvkr, *p_kr, *p_kv, *p_sc;
    cudaGetSymbolAddress((void**)&p_cq,    g_cq);
    cudaGetSymbolAddress((void**)&p_q,     g_q);
    cudaGetSymbolAddress((void**)&p_ckvkr, g_ckvkr);
    cudaGetSymbolAddress((void**)&p_kr,    g_kr);
    cudaGetSymbolAddress((void**)&p_kv,    g_kv);
    cudaGetSymbolAddress((void**)&p_sc,    g_sc);

    __nv_bfloat16 *p_xh, *p_xl, *p_cqh, *p_cql, *p_ckvh, *p_ckvl;
    __nv_bfloat16 *p_qsh, *p_qsl, *p_ksh, *p_ksl, *p_vth, *p_vtl;
    __nv_bfloat16 *p_ph, *p_pl, *p_attnh, *p_attnl;
    __nv_bfloat16 *p_wdqh, *p_wdql, *p_wuqh, *p_wuql, *p_wdkvh, *p_wdkvl;
    __nv_bfloat16 *p_wukuvh, *p_wukuvl, *p_woh, *p_wol;
    cudaGetSymbolAddress((void**)&p_xh,    g_xh);
    cudaGetSymbolAddress((void**)&p_xl,    g_xl);
    cudaGetSymbolAddress((void**)&p_cqh,   g_cqh);
    cudaGetSymbolAddress((void**)&p_cql,   g_cql);
    cudaGetSymbolAddress((void**)&p_ckvh,  g_ckvh);
    cudaGetSymbolAddress((void**)&p_ckvl,  g_ckvl);
    cudaGetSymbolAddress((void**)&p_qsh,   g_qsh);
    cudaGetSymbolAddress((void**)&p_qsl,   g_qsl);
    cudaGetSymbolAddress((void**)&p_ksh,   g_ksh);
    cudaGetSymbolAddress((void**)&p_ksl,   g_ksl);
    cudaGetSymbolAddress((void**)&p_vth,   g_vth);
    cudaGetSymbolAddress((void**)&p_vtl,   g_vtl);
    cudaGetSymbolAddress((void**)&p_ph,    g_ph);
    cudaGetSymbolAddress((void**)&p_pl,    g_pl);
    cudaGetSymbolAddress((void**)&p_attnh, g_attnh);
    cudaGetSymbolAddress((void**)&p_attnl, g_attnl);
    cudaGetSymbolAddress((void**)&p_wdqh,  g_wdqh);
    cudaGetSymbolAddress((void**)&p_wdql,  g_wdql);
    cudaGetSymbolAddress((void**)&p_wuqh,  g_wuqh);
    cudaGetSymbolAddress((void**)&p_wuql,  g_wuql);
    cudaGetSymbolAddress((void**)&p_wdkvh, g_wdkvh);
    cudaGetSymbolAddress((void**)&p_wdkvl, g_wdkvl);
    cudaGetSymbolAddress((void**)&p_wukuvh, g_wukuvh);
    cudaGetSymbolAddress((void**)&p_wukuvl, g_wukuvl);
    cudaGetSymbolAddress((void**)&p_woh,   g_woh);
    cudaGetSymbolAddress((void**)&p_wol,   g_wol);

    cudaFuncSetAttribute(hgemm3_kernel<0>, cudaFuncAttributeMaxDynamicSharedMemorySize,
                         GEMM_SMEM);
    cudaFuncSetAttribute(hgemm3_kernel<1>, cudaFuncAttributeMaxDynamicSharedMemorySize,
                         GEMM_SMEM);

    dim3 tb(32, 8);

    // ---- prep: split x, transpose+split weights ----
    split_x_kernel<<<(MTOK * 1024 / 4) / 256, 256>>>(x, p_xh, p_xl);
    transpose_split_kernel<<<dim3(4, 32),  tb>>>(w_dq_w,    1024, 128,  p_wdqh, p_wdql);
    transpose_split_kernel<<<dim3(32, 4),  tb>>>(w_uq_qr_w, 128, 1024,  p_wuqh, p_wuql);
    transpose_split_kernel<<<dim3(6, 32),  tb>>>(w_dkv_w,   1024, 192,  p_wdkvh, p_wdkvl);
    transpose_split_kernel<<<dim3(80, 4),  tb>>>(w_ukuv_w,  128, 2560,  p_wukuvh, p_wukuvl);
    transpose_split_kernel<<<dim3(32, 64), tb>>>(w_o_w,     2048, 1024, p_woh, p_wol);

    // 1) cq = x @ w_dq + b                [4096,128] K=1024
    hgemm3_kernel<0><<<dim3(1, 32, 1), 256, GEMM_SMEM>>>(
        p_xh, p_xl, 1024, 0, p_wdqh, p_wdql, 1024, 0, w_dq_b,
        p_cq, 128, 0, nullptr, nullptr, 128, 1024, 1.f);
    // 2) rmsnorm -> split cq
    rmsnorm_split_kernel<<<MTOK, 128>>>(p_cq, q_norm_w, p_cqh, p_cql);
    // 3) q = cq @ w_uq + b                [4096,1024] K=128
    hgemm3_kernel<0><<<dim3(8, 32, 1), 256, GEMM_SMEM>>>(
        p_cqh, p_cql, 128, 0, p_wuqh, p_wuql, 128, 0, w_uq_qr_b,
        p_q, 1024, 0, nullptr, nullptr, 1024, 128, 1.f);
    // 4) ckv_kr = x @ w_dkv + b           [4096,192] K=1024
    hgemm3_kernel<0><<<dim3(2, 32, 1), 256, GEMM_SMEM>>>(
        p_xh, p_xl, 1024, 0, p_wdkvh, p_wdkvl, 1024, 0, w_dkv_b,
        p_ckvkr, 192, 0, nullptr, nullptr, 192, 1024, 1.f);
    // 5) rmsnorm(ckv) split + rope(k_rope)
    post_ckvkr_kernel<<<MTOK, 128>>>(p_ckvkr, kv_norm_w, pos, p_ckvh, p_ckvl, p_kr);
    // 6) kv = ckv @ w_ukuv + b            [4096,2560] K=128
    hgemm3_kernel<0><<<dim3(20, 32, 1), 256, GEMM_SMEM>>>(
        p_ckvh, p_ckvl, 128, 0, p_wukuvh, p_wukuvl, 128, 0, w_ukuv_b,
        p_kv, 2560, 0, nullptr, nullptr, 2560, 128, 1.f);
    // 7) build q/k states (split) and V^T (split)
    build_q_split_kernel<<<(NBATCH * Ss * 128) / 256, 256>>>(p_q, pos, p_qsh, p_qsl);
    build_k_split_kernel<<<(NBATCH * Ss * 128) / 256, 256>>>(p_kv, p_kr, p_ksh, p_ksl);
    build_vT_split_kernel<<<dim3(64, 8, NBATCH), tb>>>(p_kv, p_vth, p_vtl);
    // 8) scores = scale * Q @ K^T         16x [2048,2048] K=128
    hgemm3_kernel<0><<<dim3(16, 16, NBATCH), 256, GEMM_SMEM>>>(
        p_qsh, p_qsl, 128, (long long)Ss * 128,
        p_ksh, p_ksl, 128, (long long)Ss * 128,
        nullptr,
        p_sc, Ss, (long long)Ss * Ss, nullptr, nullptr,
        Ss, 128, SCALE);
    // 9) softmax -> split P
    softmax_split_kernel<<<NBATCH * Ss, 256>>>(p_sc, p_ph, p_pl);
    // 10) attn = P @ V (split output, permuted into [B*S][H*256])
    hgemm3_kernel<1><<<dim3(2, 16, NBATCH), 256, GEMM_SMEM>>>(
        p_ph, p_pl, Ss, (long long)Ss * Ss,
        p_vth, p_vtl, Ss, (long long)256 * Ss,
        nullptr,
        nullptr, 0, 0, p_attnh, p_attnl,
        256, Ss, 1.f);
    // 11) out = attn @ w_o + b            [4096,1024] K=2048
    hgemm3_kernel<0><<<dim3(8, 32, 1), 256, GEMM_SMEM>>>(
        p_attnh, p_attnl, 2048, 0, p_woh, p_wol, 2048, 0, w_o_b,
        out, 1024, 0, nullptr, nullptr, 1024, 2048, 1.f);
}

// round 13
// speedup vs baseline: 1.9268x; 1.9268x over previous
#include <cuda_runtime.h>
#include <cuda_bf16.h>
#include <cuda_fp16.h>
#include <math.h>
#include <stdint.h>

// ---------------- problem constants ----------------
#define Bb    2
#define Ss    2048
#define MTOK  4096
#define NBATCH 16
#define SCALE 0.08838834764831845f   // 1/sqrt(128)

// ---------------- scratch (device globals; no allocation) ----------------
__device__ float g_cq[MTOK * 128];
__device__ float g_q[MTOK * 1024];
__device__ float g_ckvkr[MTOK * 192];
__device__ float g_ckv[MTOK * 128];
__device__ float g_kr[MTOK * 64];
__device__ float g_kv[MTOK * 2560];
__device__ float g_qs[NBATCH * Ss * 128];
__device__ float g_sc[(long long)NBATCH * Ss * Ss];   // 268 MB
__device__ float g_attn[MTOK * 2048];
// fp16 attention operands (single precision pass)
__device__ __half g_p16[(long long)NBATCH * Ss * Ss]; // 134 MB
__device__ __half g_v16[NBATCH * 256 * Ss];           // V^T per (b,h): [256][2048]
// pre-split bf16 B operands (hi/lo)
__device__ __nv_bfloat16 g_ks_h[NBATCH * Ss * 128];
__device__ __nv_bfloat16 g_ks_l[NBATCH * Ss * 128];
__device__ __nv_bfloat16 g_wdq_h[128 * 1024],  g_wdq_l[128 * 1024];
__device__ __nv_bfloat16 g_wuq_h[1024 * 128],  g_wuq_l[1024 * 128];
__device__ __nv_bfloat16 g_wdkv_h[192 * 1024], g_wdkv_l[192 * 1024];
__device__ __nv_bfloat16 g_wukuv_h[2560 * 128], g_wukuv_l[2560 * 128];
__device__ __nv_bfloat16 g_wo_h[1024 * 2048],  g_wo_l[1024 * 2048];

// ================= helpers =================
__device__ __forceinline__ uint32_t smem_u32(const void* p) {
    uint32_t a;
    asm("{ .reg .u64 t; cvta.to.shared.u64 t, %1; cvt.u32.u64 %0, t; }" : "=r"(a) : "l"(p));
    return a;
}

#define LDSM4(r0, r1, r2, r3, addr) \
    asm volatile("ldmatrix.sync.aligned.m8n8.x4.shared.b16 {%0,%1,%2,%3}, [%4];" \
                 : "=r"(r0), "=r"(r1), "=r"(r2), "=r"(r3) : "r"(addr))

#define MMA_BF16(d, a, b) \
    asm volatile("mma.sync.aligned.m16n8k16.row.col.f32.bf16.bf16.f32 " \
                 "{%0,%1,%2,%3}, {%4,%5,%6,%7}, {%8,%9}, {%0,%1,%2,%3};" \
                 : "+f"((d)[0]), "+f"((d)[1]), "+f"((d)[2]), "+f"((d)[3]) \
                 : "r"((a)[0]), "r"((a)[1]), "r"((a)[2]), "r"((a)[3]), \
                   "r"((b)[0]), "r"((b)[1]))

#define MMA_FP16(d, a, b) \
    asm volatile("mma.sync.aligned.m16n8k16.row.col.f32.f16.f16.f32 " \
                 "{%0,%1,%2,%3}, {%4,%5,%6,%7}, {%8,%9}, {%0,%1,%2,%3};" \
                 : "+f"((d)[0]), "+f"((d)[1]), "+f"((d)[2]), "+f"((d)[3]) \
                 : "r"((a)[0]), "r"((a)[1]), "r"((a)[2]), "r"((a)[3]), \
                   "r"((b)[0]), "r"((b)[1]))

__device__ __forceinline__ void split2(float x, float y, uint32_t& hi, uint32_t& lo) {
    __nv_bfloat16 hx = __float2bfloat16(x), hy = __float2bfloat16(y);
    __nv_bfloat16 lx = __float2bfloat16(x - __bfloat162float(hx));
    __nv_bfloat16 ly = __float2bfloat16(y - __bfloat162float(hy));
    __nv_bfloat162 h = __halves2bfloat162(hx, hy);
    __nv_bfloat162 l = __halves2bfloat162(lx, ly);
    hi = *reinterpret_cast<uint32_t*>(&h);
    lo = *reinterpret_cast<uint32_t*>(&l);
}
__device__ __forceinline__ void cpa16(uint32_t dst, const void* src) {
    asm volatile("cp.async.cg.shared.global [%0], [%1], 16;" :: "r"(dst), "l"(src));
}
#define CP_COMMIT() asm volatile("cp.async.commit_group;" ::: "memory")
#define CP_WAIT0()  asm volatile("cp.async.wait_group 0;" ::: "memory")

// ================= double-buffered split-bf16 GEMM (R9, 910us, verbatim) ====
// C[m,n] = alpha * sum_k A[m,k]*B[n,k] + bias[n]
// A fp32 (split in-kernel), B pre-split bf16 hi/lo (cp.async).
#define SROW 40                       // bf16 elems per smem row (80 B)
#define TILE_B ((uint32_t)(128 * SROW * 2))   // 10240 bytes per matrix tile
#define STAGE_B (4 * TILE_B)                  // Ah, Al, Bh, Bl
#define GEMM_SMEM (2 * STAGE_B)               // 81920

__global__ void __launch_bounds__(256)
hgemm2_kernel(const float* __restrict__ A, int lda, long long sA,
              const __nv_bfloat16* __restrict__ Bh,
              const __nv_bfloat16* __restrict__ Bl, int ldb, long long sB,
              const float* __restrict__ bias,
              float* __restrict__ C, int ldc, long long sC,
              int N, int K, float alpha)
{
    extern __shared__ char smraw[];
    const uint32_t sb = smem_u32(smraw);

    const int tid  = threadIdx.x;
    const int lane = tid & 31;
    const int wid  = tid >> 5;
    const int wm   = wid & 1;
    const int wn   = wid >> 1;

    const int z  = blockIdx.z;
    A  += z * sA;
    Bh += z * sB;
    Bl += z * sB;
    const int m0 = blockIdx.y * 128;
    const int n0 = blockIdx.x * 128;

    const int lr  = tid >> 2;
    const int lc4 = (tid & 3) * 2;
    float4 pa[4];

    float acc[4][4][4];
#pragma unroll
    for (int i = 0; i < 4; i++)
#pragma unroll
        for (int j = 0; j < 4; j++)
#pragma unroll
            for (int c = 0; c < 4; c++) acc[i][j][c] = 0.f;

#define BUF_AH(t) (sb + (t) * STAGE_B)
#define BUF_AL(t) (sb + (t) * STAGE_B + TILE_B)
#define BUF_BH(t) (sb + (t) * STAGE_B + 2 * TILE_B)
#define BUF_BL(t) (sb + (t) * STAGE_B + 3 * TILE_B)

#define PREFETCH_A(kt)                                                          \
    {                                                                           \
        _Pragma("unroll")                                                       \
        for (int u = 0; u < 4; u++) {                                           \
            int r  = lr + (u >> 1) * 64;                                        \
            int c4 = lc4 + (u & 1);                                             \
            pa[u] = *reinterpret_cast<const float4*>(                           \
                A + (long long)(m0 + r) * lda + (kt) + c4 * 4);                 \
        }                                                                       \
    }

#define STORE_A(t)                                                              \
    {                                                                           \
        _Pragma("unroll")                                                       \
        for (int u = 0; u < 4; u++) {                                           \
            int r = lr + (u >> 1) * 64;                                         \
            int c = (lc4 + (u & 1)) * 4;                                        \
            uint32_t h0, l0, h1, l1;                                            \
            split2(pa[u].x, pa[u].y, h0, l0);                                   \
            split2(pa[u].z, pa[u].w, h1, l1);                                   \
            uint32_t off = (uint32_t)(r * SROW + c) * 2;                        \
            asm volatile("st.shared.v2.b32 [%0], {%1,%2};" ::                   \
                         "r"(BUF_AH(t) + off), "r"(h0), "r"(h1) : "memory");    \
            asm volatile("st.shared.v2.b32 [%0], {%1,%2};" ::                   \
                         "r"(BUF_AL(t) + off), "r"(l0), "r"(l1) : "memory");    \
        }                                                                       \
    }

#define LOAD_B(kt, t)                                                           \
    {                                                                           \
        _Pragma("unroll")                                                       \
        for (int u = 0; u < 2; u++) {                                           \
            int id = tid * 2 + u;                                               \
            int r  = id >> 2;                                                   \
            int cc = (id & 3) * 8;                                              \
            uint32_t doff = (uint32_t)(r * SROW + cc) * 2;                      \
            int gn = n0 + r;                                                    \
            if (gn < N) {                                                       \
                cpa16(BUF_BH(t) + doff, Bh + (long long)gn * ldb + (kt) + cc);  \
                cpa16(BUF_BL(t) + doff, Bl + (long long)gn * ldb + (kt) + cc);  \
            } else {                                                            \
                asm volatile("st.shared.v4.b32 [%0], {%1,%1,%1,%1};" ::         \
                             "r"(BUF_BH(t) + doff), "r"(0) : "memory");         \
                asm volatile("st.shared.v4.b32 [%0], {%1,%1,%1,%1};" ::         \
                             "r"(BUF_BL(t) + doff), "r"(0) : "memory");         \
            }                                                                   \
        }                                                                       \
    }

    PREFETCH_A(0);
    LOAD_B(0, 0);
    CP_COMMIT();
    STORE_A(0);
    CP_WAIT0();
    __syncthreads();

    const int nk = K >> 5;
    for (int s = 0; s < nk; s++) {
        const int cur = s & 1, nxt = cur ^ 1;
        if (s + 1 < nk) {
            PREFETCH_A((s + 1) << 5);
            LOAD_B((s + 1) << 5, nxt);
            CP_COMMIT();
        }

        const uint32_t uAh = BUF_AH(cur), uAl = BUF_AL(cur);
        const uint32_t uBh = BUF_BH(cur), uBl = BUF_BL(cur);
#pragma unroll
        for (int ks = 0; ks < 2; ks++) {
            uint32_t bh[4][2], bl[4][2];
#pragma unroll
            for (int jp = 0; jp < 2; jp++) {
                int rowb = wn * 32 + jp * 16 + (lane & 7) + ((lane & 16) >> 1);
                int kc   = ks * 16 + (lane & 8);
                uint32_t off = (uint32_t)(rowb * SROW + kc) * 2;
                LDSM4(bh[jp * 2][0], bh[jp * 2][1], bh[jp * 2 + 1][0], bh[jp * 2 + 1][1],
                      uBh + off);
                LDSM4(bl[jp * 2][0], bl[jp * 2][1], bl[jp * 2 + 1][0], bl[jp * 2 + 1][1],
                      uBl + off);
            }
#pragma unroll
            for (int i = 0; i < 4; i++) {
                int rowa = wm * 64 + i * 16 + (lane & 7) + (lane & 8);
                int kc   = ks * 16 + ((lane & 16) >> 1);
                uint32_t off = (uint32_t)(rowa * SROW + kc) * 2;
                uint32_t ah[4], al[4];
                LDSM4(ah[0], ah[1], ah[2], ah[3], uAh + off);
                LDSM4(al[0], al[1], al[2], al[3], uAl + off);
#pragma unroll
                for (int j = 0; j < 4; j++) {
                    MMA_BF16(acc[i][j], ah, bh[j]);
                    MMA_BF16(acc[i][j], ah, bl[j]);
                    MMA_BF16(acc[i][j], al, bh[j]);
                }
            }
        }

        if (s + 1 < nk) {
            STORE_A(nxt);
            CP_WAIT0();
        }
        __syncthreads();
    }

    float* Cp = C + z * sC;
#pragma unroll
    for (int j = 0; j < 4; j++) {
        int col = n0 + wn * 32 + j * 8 + (lane & 3) * 2;
        if (col >= N) continue;
        float b0 = 0.f, b1 = 0.f;
        if (bias) { b0 = bias[col]; b1 = bias[col + 1]; }
#pragma unroll
        for (int i = 0; i < 4; i++) {
            int row = m0 + wm * 64 + i * 16 + (lane >> 2);
            float2 v0 = make_float2(acc[i][j][0] * alpha + b0,
                                    acc[i][j][1] * alpha + b1);
            float2 v1 = make_float2(acc[i][j][2] * alpha + b0,
                                    acc[i][j][3] * alpha + b1);
            *reinterpret_cast<float2*>(Cp + (long long)row * ldc + col)       = v0;
            *reinterpret_cast<float2*>(Cp + (long long)(row + 8) * ldc + col) = v1;
        }
    }
#undef BUF_AH
#undef BUF_AL
#undef BUF_BH
#undef BUF_BL
#undef PREFETCH_A
#undef STORE_A
#undef LOAD_B
}

// ================= single-pass fp16 PV GEMM =================
// attn = P @ V ; A = P fp16 [z][2048][2048], B = V^T fp16 [z][256][2048].
// Output fp32 written permuted into [b*Ss + m][h*256 + n] (z = b*8+h).
#define TILE16 ((uint32_t)(128 * SROW * 2))   // 10240 B (fp16 tile)
#define STAGE16 (2 * TILE16)                  // A, B
#define PV_SMEM (2 * STAGE16)                 // 40960

__global__ void __launch_bounds__(256)
hgemm_pv_kernel(const __half* __restrict__ Ap, int lda, long long sA,
                const __half* __restrict__ Bp, int ldb, long long sB,
                float* __restrict__ outp, int N, int K)
{
    extern __shared__ char smraw[];
    const uint32_t sb = smem_u32(smraw);

    const int tid  = threadIdx.x;
    const int lane = tid & 31;
    const int wid  = tid >> 5;
    const int wm   = wid & 1;
    const int wn   = wid >> 1;

    const int z  = blockIdx.z;
    Ap += z * sA;
    Bp += z * sB;
    const int m0 = blockIdx.y * 128;
    const int n0 = blockIdx.x * 128;

    float acc[4][4][4];
#pragma unroll
    for (int i = 0; i < 4; i++)
#pragma unroll
        for (int j = 0; j < 4; j++)
#pragma unroll
            for (int c = 0; c < 4; c++) acc[i][j][c] = 0.f;

#define BUF16_A(t) (sb + (t) * STAGE16)
#define BUF16_B(t) (sb + (t) * STAGE16 + TILE16)

#define LOAD16(kt, t)                                                           \
    {                                                                           \
        _Pragma("unroll")                                                       \
        for (int u = 0; u < 2; u++) {                                           \
            int id = tid * 2 + u;                                               \
            int r  = id >> 2;                                                   \
            int cc = (id & 3) * 8;                                              \
            uint32_t doff = (uint32_t)(r * SROW + cc) * 2;                      \
            cpa16(BUF16_A(t) + doff, Ap + (long long)(m0 + r) * lda + (kt) + cc); \
            cpa16(BUF16_B(t) + doff, Bp + (long long)(n0 + r) * ldb + (kt) + cc); \
        }                                                                       \
    }

    LOAD16(0, 0);
    CP_COMMIT();
    CP_WAIT0();
    __syncthreads();

    const int nk = K >> 5;
    for (int s = 0; s < nk; s++) {
        const int cur = s & 1, nxt = cur ^ 1;
        if (s + 1 < nk) {
            LOAD16((s + 1) << 5, nxt);
            CP_COMMIT();
        }

        const uint32_t uA = BUF16_A(cur), uB = BUF16_B(cur);
#pragma unroll
        for (int ks = 0; ks < 2; ks++) {
            uint32_t bf[4][2];
#pragma unroll
            for (int jp = 0; jp < 2; jp++) {
                int rowb = wn * 32 + jp * 16 + (lane & 7) + ((lane & 16) >> 1);
                int kc   = ks * 16 + (lane & 8);
                uint32_t off = (uint32_t)(rowb * SROW + kc) * 2;
                LDSM4(bf[jp * 2][0], bf[jp * 2][1], bf[jp * 2 + 1][0], bf[jp * 2 + 1][1],
                      uB + off);
            }
#pragma unroll
            for (int i = 0; i < 4; i++) {
                int rowa = wm * 64 + i * 16 + (lane & 7) + (lane & 8);
                int kc   = ks * 16 + ((lane & 16) >> 1);
                uint32_t off = (uint32_t)(rowa * SROW + kc) * 2;
                uint32_t af[4];
                LDSM4(af[0], af[1], af[2], af[3], uA + off);
#pragma unroll
                for (int j = 0; j < 4; j++)
                    MMA_FP16(acc[i][j], af, bf[j]);
            }
        }

        if (s + 1 < nk) CP_WAIT0();
        __syncthreads();
    }

    // permuted epilogue: z = b*8 + h
    float* Cp = outp + ((long long)(z >> 3) * Ss) * 2048 + (z & 7) * 256;
#pragma unroll
    for (int j = 0; j < 4; j++) {
        int col = n0 + wn * 32 + j * 8 + (lane & 3) * 2;
#pragma unroll
        for (int i = 0; i < 4; i++) {
            int row = m0 + wm * 64 + i * 16 + (lane >> 2);
            float2 v0 = make_float2(acc[i][j][0], acc[i][j][1]);
            float2 v1 = make_float2(acc[i][j][2], acc[i][j][3]);
            *reinterpret_cast<float2*>(Cp + (long long)row * 2048 + col)       = v0;
            *reinterpret_cast<float2*>(Cp + (long long)(row + 8) * 2048 + col) = v1;
        }
    }
#undef BUF16_A
#undef BUF16_B
#undef LOAD16
}

// ================= transpose + split: fp32 [R][C] -> bf16 hi/lo [C][R] =====
__global__ void transpose_split_kernel(const float* __restrict__ src, int R, int Cc,
                                       __nv_bfloat16* __restrict__ dh,
                                       __nv_bfloat16* __restrict__ dl)
{
    __shared__ float t[32][33];
    int r0 = blockIdx.y * 32, c0 = blockIdx.x * 32;
    int tx = threadIdx.x, ty = threadIdx.y;    // 32 x 8
#pragma unroll
    for (int i = 0; i < 32; i += 8)
        if (r0 + ty + i < R && c0 + tx < Cc)
            t[ty + i][tx] = src[(long long)(r0 + ty + i) * Cc + c0 + tx];
    __syncthreads();
#pragma unroll
    for (int i = 0; i < 32; i += 8)
        if (c0 + ty + i < Cc && r0 + tx < R) {
            float v = t[tx][ty + i];
            __nv_bfloat16 h = __float2bfloat16(v);
            long long o = (long long)(c0 + ty + i) * R + r0 + tx;
            dh[o] = h;
            dl[o] = __float2bfloat16(v - __bfloat162float(h));
        }
}

// V^T fp16: vt[z][d][s] = kv[(b*2048+s)*2560 + 512 + h*256 + d]
__global__ void build_vT_half_kernel(const float* __restrict__ kv,
                                     __half* __restrict__ vt)
{
    __shared__ float t[32][33];
    int z = blockIdx.z, b = z >> 3, h = z & 7;
    const float* src = kv + (long long)b * 2048 * 2560 + 512 + h * 256;
    long long dbase = (long long)z * 256 * 2048;
    int s0 = blockIdx.x * 32, d0 = blockIdx.y * 32;
    int tx = threadIdx.x, ty = threadIdx.y;
#pragma unroll
    for (int i = 0; i < 32; i += 8)
        t[ty + i][tx] = src[(long long)(s0 + ty + i) * 2560 + d0 + tx];
    __syncthreads();
#pragma unroll
    for (int i = 0; i < 32; i += 8)
        vt[dbase + (long long)(d0 + ty + i) * 2048 + s0 + tx] =
            __float2half_rn(t[tx][ty + i]);
}

// ================= elementwise kernels =================
__global__ void rmsnorm128_kernel(float* __restrict__ buf, const float* __restrict__ w)
{
    int row = blockIdx.x, tid = threadIdx.x;
    float v = buf[row * 128 + tid];
    float ss = v * v;
#pragma unroll
    for (int o = 16; o; o >>= 1) ss += __shfl_xor_sync(0xffffffffu, ss, o);
    __shared__ float red[4];
    if ((tid & 31) == 0) red[tid >> 5] = ss;
    __syncthreads();
    float tot = red[0] + red[1] + red[2] + red[3];
    float rs = rsqrtf(tot * (1.f / 128.f) + 1e-8f);
    buf[row * 128 + tid] = w[tid] * v * rs;
}

__global__ void post_ckvkr_kernel(const float* __restrict__ in,
                                  const float* __restrict__ w,
                                  const int* __restrict__ pos,
                                  float* __restrict__ ckv,
                                  float* __restrict__ kr)
{
    int row = blockIdx.x, tid = threadIdx.x;
    float v = in[row * 192 + tid];
    float ss = v * v;
#pragma unroll
    for (int o = 16; o; o >>= 1) ss += __shfl_xor_sync(0xffffffffu, ss, o);
    __shared__ float red[4];
    if ((tid & 31) == 0) red[tid >> 5] = ss;
    __syncthreads();
    float tot = red[0] + red[1] + red[2] + red[3];
    float rs = rsqrtf(tot * (1.f / 128.f) + 1e-8f);
    ckv[row * 128 + tid] = w[tid] * v * rs;

    if (tid < 32) {
        float xe = in[row * 192 + 128 + 2 * tid];
        float xo = in[row * 192 + 128 + 2 * tid + 1];
        float invf = powf(10000.f, -(float)(2 * tid) / 64.f);
        float ang = (float)pos[row] * invf;
        float s, c;
        sincosf(ang, &s, &c);
        kr[row * 64 + 2 * tid]     = xe * c - xo * s;
        kr[row * 64 + 2 * tid + 1] = xe * s + xo * c;
    }
}

__global__ void build_q_kernel(const float* __restrict__ q,
                               const int* __restrict__ pos,
                               float* __restrict__ qs)
{
    int idx = blockIdx.x * blockDim.x + threadIdx.x;
    int d = idx & 127;
    int t = idx >> 7;
    int qp = t & (Ss - 1);
    int zz = t >> 11;
    int b = zz >> 3, h = zz & 7;
    int row = b * Ss + qp;
    float val;
    if (d < 96) {
        val = q[row * 1024 + h * 96 + d];
    } else {
        int r = d - 96;
        int i = r >> 1;
        float xe = q[row * 1024 + 768 + h * 32 + 2 * i];
        float xo = q[row * 1024 + 768 + h * 32 + 2 * i + 1];
        float invf = powf(10000.f, -(float)(2 * i) / 32.f);
        float ang = (float)pos[row] * invf;
        float s, c;
        sincosf(ang, &s, &c);
        val = (r & 1) ? (xe * s + xo * c) : (xe * c - xo * s);
    }
    qs[idx] = val;
}

__global__ void build_k_split_kernel(const float* __restrict__ kv,
                                     const float* __restrict__ kr,
                                     __nv_bfloat16* __restrict__ kh,
                                     __nv_bfloat16* __restrict__ kl)
{
    int idx = blockIdx.x * blockDim.x + threadIdx.x;
    int d = idx & 127;
    int t = idx >> 7;
    int qp = t & (Ss - 1);
    int zz = t >> 11;
    int b = zz >> 3, h = zz & 7;
    int row = b * Ss + qp;
    float v = (d < 64) ? kv[row * 2560 + h * 64 + d] : kr[row * 64 + (d - 64)];
    __nv_bfloat16 hh = __float2bfloat16(v);
    kh[idx] = hh;
    kl[idx] = __float2bfloat16(v - __bfloat162float(hh));
}

// row softmax over 2048 cols -> fp16 P. Thread owns 8 CONTIGUOUS columns.
__global__ void softmax_half_kernel(const float* __restrict__ sc,
                                    __half* __restrict__ p16)
{
    const float* p = sc + (long long)blockIdx.x * 2048;
    __half* o = p16 + (long long)blockIdx.x * 2048;
    int tid = threadIdx.x;
    float v[8];
    float4 a = *reinterpret_cast<const float4*>(p + tid * 8);
    float4 b = *reinterpret_cast<const float4*>(p + tid * 8 + 4);
    v[0] = a.x; v[1] = a.y; v[2] = a.z; v[3] = a.w;
    v[4] = b.x; v[5] = b.y; v[6] = b.z; v[7] = b.w;
    float m = v[0];
#pragma unroll
    for (int i = 1; i < 8; i++) m = fmaxf(m, v[i]);
#pragma unroll
    for (int of = 16; of; of >>= 1) m = fmaxf(m, __shfl_xor_sync(0xffffffffu, m, of));
    __shared__ float redm[8];
    int lane = tid & 31, w = tid >> 5;
    if (lane == 0) redm[w] = m;
    __syncthreads();
    m = redm[0];
#pragma unroll
    for (int i = 1; i < 8; i++) m = fmaxf(m, redm[i]);
    float sum = 0.f;
#pragma unroll
    for (int i = 0; i < 8; i++) { v[i] = __expf(v[i] - m); sum += v[i]; }
#pragma unroll
    for (int of = 16; of; of >>= 1) sum += __shfl_xor_sync(0xffffffffu, sum, of);
    __shared__ float reds[8];
    if (lane == 0) reds[w] = sum;
    __syncthreads();
    sum = 0.f;
#pragma unroll
    for (int i = 0; i < 8; i++) sum += reds[i];
    float inv = 1.f / sum;
    __half h[8];
#pragma unroll
    for (int i = 0; i < 8; i++) h[i] = __float2half_rn(v[i] * inv);
    *reinterpret_cast<uint4*>(o + tid * 8) = *reinterpret_cast<uint4*>(h);
}

// ================= launch =================
extern "C" void kernel_launch(void* const* d_in, const int* in_sizes, int n_in,
                              void* d_out, int out_size)
{
    const float* x         = (const float*)d_in[0];
    const int*   pos       = (const int*)  d_in[1];
    const float* w_dq_w    = (const float*)d_in[2];
    const float* w_dq_b    = (const float*)d_in[3];
    const float* q_norm_w  = (const float*)d_in[4];
    const float* w_uq_qr_w = (const float*)d_in[5];
    const float* w_uq_qr_b = (const float*)d_in[6];
    const float* w_dkv_w   = (const float*)d_in[7];
    const float* w_dkv_b   = (const float*)d_in[8];
    const float* kv_norm_w = (const float*)d_in[9];
    const float* w_ukuv_w  = (const float*)d_in[10];
    const float* w_ukuv_b  = (const float*)d_in[11];
    const float* w_o_w     = (const float*)d_in[12];
    const float* w_o_b     = (const float*)d_in[13];
    float* out = (float*)d_out;

    float *p_cq, *p_q, *p_ckvkr, *p_ckv, *p_kr, *p_kv, *p_qs, *p_sc, *p_attn;
    __half *p_p16, *p_v16;
    __nv_bfloat16 *p_ksh, *p_ksl;
    __nv_bfloat16 *p_wdqh, *p_wdql, *p_wuqh, *p_wuql, *p_wdkvh, *p_wdkvl;
    __nv_bfloat16 *p_wukuvh, *p_wukuvl, *p_woh, *p_wol;
    cudaGetSymbolAddress((void**)&p_cq,    g_cq);
    cudaGetSymbolAddress((void**)&p_q,     g_q);
    cudaGetSymbolAddress((void**)&p_ckvkr, g_ckvkr);
    cudaGetSymbolAddress((void**)&p_ckv,   g_ckv);
    cudaGetSymbolAddress((void**)&p_kr,    g_kr);
    cudaGetSymbolAddress((void**)&p_kv,    g_kv);
    cudaGetSymbolAddress((void**)&p_qs,    g_qs);
    cudaGetSymbolAddress((void**)&p_sc,    g_sc);
    cudaGetSymbolAddress((void**)&p_attn,  g_attn);
    cudaGetSymbolAddress((void**)&p_p16,   g_p16);
    cudaGetSymbolAddress((void**)&p_v16,   g_v16);
    cudaGetSymbolAddress((void**)&p_ksh,   g_ks_h);
    cudaGetSymbolAddress((void**)&p_ksl,   g_ks_l);
    cudaGetSymbolAddress((void**)&p_wdqh,  g_wdq_h);
    cudaGetSymbolAddress((void**)&p_wdql,  g_wdq_l);
    cudaGetSymbolAddress((void**)&p_wuqh,  g_wuq_h);
    cudaGetSymbolAddress((void**)&p_wuql,  g_wuq_l);
    cudaGetSymbolAddress((void**)&p_wdkvh, g_wdkv_h);
    cudaGetSymbolAddress((void**)&p_wdkvl, g_wdkv_l);
    cudaGetSymbolAddress((void**)&p_wukuvh, g_wukuv_h);
    cudaGetSymbolAddress((void**)&p_wukuvl, g_wukuv_l);
    cudaGetSymbolAddress((void**)&p_woh,   g_wo_h);
    cudaGetSymbolAddress((void**)&p_wol,   g_wo_l);

    cudaFuncSetAttribute(hgemm2_kernel, cudaFuncAttributeMaxDynamicSharedMemorySize,
                         GEMM_SMEM);
    cudaFuncSetAttribute(hgemm_pv_kernel, cudaFuncAttributeMaxDynamicSharedMemorySize,
                         PV_SMEM);

    dim3 tb(32, 8);

    // ---- weight transpose + split ----
    transpose_split_kernel<<<dim3(4, 32),  tb>>>(w_dq_w,    1024, 128,  p_wdqh, p_wdql);
    transpose_split_kernel<<<dim3(32, 4),  tb>>>(w_uq_qr_w, 128, 1024,  p_wuqh, p_wuql);
    transpose_split_kernel<<<dim3(6, 32),  tb>>>(w_dkv_w,   1024, 192,  p_wdkvh, p_wdkvl);
    transpose_split_kernel<<<dim3(80, 4),  tb>>>(w_ukuv_w,  128, 2560,  p_wukuvh, p_wukuvl);
    transpose_split_kernel<<<dim3(32, 64), tb>>>(w_o_w,     2048, 1024, p_woh, p_wol);

    // 1) cq = x @ w_dq + b
    hgemm2_kernel<<<dim3(1, 32, 1), 256, GEMM_SMEM>>>(
        x, 1024, 0, p_wdqh, p_wdql, 1024, 0, w_dq_b, p_cq, 128, 0, 128, 1024, 1.f);
    // 2) rmsnorm
    rmsnorm128_kernel<<<MTOK, 128>>>(p_cq, q_norm_w);
    // 3) q = cq @ w_uq + b
    hgemm2_kernel<<<dim3(8, 32, 1), 256, GEMM_SMEM>>>(
        p_cq, 128, 0, p_wuqh, p_wuql, 128, 0, w_uq_qr_b, p_q, 1024, 0, 1024, 128, 1.f);
    // 4) ckv_kr = x @ w_dkv + b
    hgemm2_kernel<<<dim3(2, 32, 1), 256, GEMM_SMEM>>>(
        x, 1024, 0, p_wdkvh, p_wdkvl, 1024, 0, w_dkv_b, p_ckvkr, 192, 0, 192, 1024, 1.f);
    // 5) rmsnorm(ckv) + rope(k_rope)
    post_ckvkr_kernel<<<MTOK, 128>>>(p_ckvkr, kv_norm_w, pos, p_ckv, p_kr);
    // 6) kv = ckv @ w_ukuv + b
    hgemm2_kernel<<<dim3(20, 32, 1), 256, GEMM_SMEM>>>(
        p_ckv, 128, 0, p_wukuvh, p_wukuvl, 128, 0, w_ukuv_b, p_kv, 2560, 0, 2560, 128, 1.f);
    // 7) build q states (fp32), k states (split bf16), V^T (fp16)
    build_q_kernel<<<(NBATCH * Ss * 128) / 256, 256>>>(p_q, pos, p_qs);
    build_k_split_kernel<<<(NBATCH * Ss * 128) / 256, 256>>>(p_kv, p_kr, p_ksh, p_ksl);
    build_vT_half_kernel<<<dim3(64, 8, NBATCH), tb>>>(p_kv, p_v16);
    // 8) scores = scale * Q @ K^T (3-pass bf16, fp32 out)
    hgemm2_kernel<<<dim3(16, 16, NBATCH), 256, GEMM_SMEM>>>(
        p_qs, 128, (long long)Ss * 128,
        p_ksh, p_ksl, 128, (long long)Ss * 128,
        nullptr,
        p_sc, Ss, (long long)Ss * Ss,
        Ss, 128, SCALE);
    // 9) softmax -> fp16 P
    softmax_half_kernel<<<NBATCH * Ss, 256>>>(p_sc, p_p16);
    // 10) attn = P @ V (1-pass fp16, permuted fp32 out)
    hgemm_pv_kernel<<<dim3(2, 16, NBATCH), 256, PV_SMEM>>>(
        p_p16, Ss, (long long)Ss * Ss,
        p_v16, Ss, (long long)256 * Ss,
        p_attn, 256, Ss);
    // 11) out = attn @ w_o + b (3-pass bf16)
    hgemm2_kernel<<<dim3(8, 32, 1), 256, GEMM_SMEM>>>(
        p_attn, 2048, 0, p_woh, p_wol, 2048, 0, w_o_b, out, 1024, 0, 1024, 2048, 1.f);
}